// round 9
// baseline (speedup 1.0000x reference)
#include <cuda_runtime.h>
#include <cuda_bf16.h>
#include <cstdint>
#include <mma.h>
using namespace nvcuda;

#define RCH 64
#define GCH 128
#define ACH 80
#define SCH 64
#define TT 8192
#define BB 8
#define NPOS (BB*TT)          // 65536
#define NLAYERS 30
#define NT 128                // positions per block tile
#define NPAD 136              // padded position stride (elements)
#define THR 512
#define WPERL 43008           // 336*128 weights per layer

// smem (bytes):
//   fsm f32 overlay:           [0, 69632)
//   W staging (<=45056):       [0, 45056)      (phase-disjoint with fsm)
//   X/Z staging:               [69632, 113152)
#define SM_X_OFF 69632
#define SMEM_TOTAL 113152

__device__ float g_xa[BB*RCH*TT];
__device__ float g_xb[BB*RCH*TT];
__device__ float g_skip[BB*SCH*TT];

// pre-split weights, chunk-contiguous per layer:
// tap0 [0,8192), tap1 [8192,16384), tap2 [16384,24576),
// aux [24576,34816) (m*80+kk), out [34816,43008) (m*64+kk)
__device__ __nv_bfloat16 g_wh[(size_t)NLAYERS * WPERL];
__device__ __nv_bfloat16 g_wl[(size_t)NLAYERS * WPERL];

static __device__ __forceinline__ float tanhapx(float x) {
    float r; asm("tanh.approx.f32 %0, %1;" : "=f"(r) : "f"(x)); return r;
}
static __device__ __forceinline__ float gatef(float a, float b) {
    return tanhapx(a) * (0.5f * tanhapx(0.5f * b) + 0.5f);
}

// ---------------------------------------------------------------------------
__global__ void k_prep(const float* __restrict__ cw, const float* __restrict__ aw,
                       const float* __restrict__ ow) {
    int idx = blockIdx.x * blockDim.x + threadIdx.x;
    if (idx >= NLAYERS * WPERL) return;
    int j = idx % WPERL;
    int l = idx / WPERL;
    float v;
    if (j < 24576) {
        int tap = j >> 13, jj = j & 8191;
        int m = jj >> 6, kk = jj & 63;
        v = cw[((size_t)(l * GCH + m) * RCH + kk) * 3 + tap];
    } else if (j < 34816) {
        int jj = j - 24576;
        int m = jj / 80, kk = jj - m * 80;
        v = aw[(size_t)(l * GCH + m) * ACH + kk];
    } else {
        int jj = j - 34816;
        int m = jj >> 6, kk = jj & 63;
        v = ow[(size_t)(l * GCH + m) * 64 + kk];
    }
    __nv_bfloat16 h = __float2bfloat16(v);
    __nv_bfloat16 lo = __float2bfloat16(v - __bfloat162float(h));
    g_wh[idx] = h;
    g_wl[idx] = lo;
}

// ---------------------------------------------------------------------------
__global__ void k_first(const float* __restrict__ x,
                        const float* __restrict__ fw,
                        const float* __restrict__ fb) {
    int idx = blockIdx.x * blockDim.x + threadIdx.x;
    int r = idx >> 16;
    int p = idx & (NPOS - 1);
    int b = p >> 13;
    int t = p & (TT - 1);
    float v = fw[r] * x[p] + fb[r];
    g_xa[(b * RCH + r) * TT + t] = v;
    g_skip[(b * SCH + r) * TT + t] = 0.f;
}

// ---------------------------------------------------------------------------
// division-free W staging: 128 x S bf16 (hi & lo) -> SPAD-strided smem
// ---------------------------------------------------------------------------
template<int S, int SPAD>
static __device__ __forceinline__ void stage_w(
        const __nv_bfloat16* __restrict__ gh,
        const __nv_bfloat16* __restrict__ gl,
        __nv_bfloat16* wa, int tid) {
    const unsigned int* sh = (const unsigned int*)gh;
    const unsigned int* sl = (const unsigned int*)gl;
    unsigned int* dh = (unsigned int*)wa;
    unsigned int* dl = dh + 128 * (SPAD / 2);
    constexpr int s2 = S / 2, sp2 = SPAD / 2;
#pragma unroll 1
    for (int idx = tid; idx < 128 * s2; idx += THR) {
        int m = idx / s2, kp = idx - m * s2;
        dh[m * sp2 + kp] = sh[idx];
        dl[m * sp2 + kp] = sl[idx];
    }
}

// ---------------------------------------------------------------------------
// bf16x3 mma over one staged chunk. acc[4] covers n0..n0+63.
// ---------------------------------------------------------------------------
template<int SPAD, int KS>
static __device__ __forceinline__ void mma_chunk(
        wmma::fragment<wmma::accumulator, 16, 16, 16, float> (&acc)[4],
        const __nv_bfloat16* __restrict__ wh, const __nv_bfloat16* __restrict__ wl,
        const __nv_bfloat16* __restrict__ xh, const __nv_bfloat16* __restrict__ xl,
        int m0, int n0) {
#pragma unroll 1
    for (int ks = 0; ks < KS; ks++) {
        wmma::fragment<wmma::matrix_a, 16, 16, 16, __nv_bfloat16, wmma::row_major> ah, al;
        wmma::load_matrix_sync(ah, wh + m0 * SPAD + 16 * ks, SPAD);
        wmma::load_matrix_sync(al, wl + m0 * SPAD + 16 * ks, SPAD);
#pragma unroll
        for (int nt = 0; nt < 4; nt++) {
            wmma::fragment<wmma::matrix_b, 16, 16, 16, __nv_bfloat16, wmma::row_major> bf;
            const int bo = 16 * ks * NPAD + n0 + 16 * nt;
            wmma::load_matrix_sync(bf, xh + bo, NPAD);
            wmma::mma_sync(acc[nt], ah, bf, acc[nt]);
            wmma::mma_sync(acc[nt], al, bf, acc[nt]);
            wmma::load_matrix_sync(bf, xl + bo, NPAD);
            wmma::mma_sync(acc[nt], ah, bf, acc[nt]);
        }
    }
}

// ---------------------------------------------------------------------------
// fused layer, tensor-core path. warp: m0 = (w&7)*16, n0 = (w>>3)*64,
// acc[4] fragments at n0 + {0,16,32,48}.
// ---------------------------------------------------------------------------
__global__ void __launch_bounds__(THR, 2)
k_layer(int l, int d, int flip,
        const float* __restrict__ conv_b, const float* __restrict__ out_b,
        const float* __restrict__ cond,   const float* __restrict__ mask) {
    extern __shared__ char smraw[];
    __nv_bfloat16* wa  = (__nv_bfloat16*)smraw;                 // W staging
    __nv_bfloat16* xbh = (__nv_bfloat16*)(smraw + SM_X_OFF);    // X/Z staging
    float* fsm = (float*)smraw;                                 // H / O overlay

    const float* xin  = flip ? g_xb : g_xa;
    float*       xout = flip ? g_xa : g_xb;

    const int tid  = threadIdx.x;
    const int wid  = tid >> 5;
    const int m0   = (wid & 7) * 16;
    const int n0   = (wid >> 3) * 64;
    const int p0   = blockIdx.x * NT;
    const int b    = p0 >> 13;
    const int tb   = p0 & (TT - 1);

    const __nv_bfloat16* gwh = g_wh + (size_t)l * WPERL;
    const __nv_bfloat16* gwl = g_wl + (size_t)l * WPERL;

    wmma::fragment<wmma::accumulator, 16, 16, 16, float> acc[4];
#pragma unroll
    for (int i = 0; i < 4; i++) wmma::fill_fragment(acc[i], 0.f);

    // ===== GEMM1 conv taps (S=64) ============================================
#pragma unroll 1
    for (int ch = 0; ch < 3; ch++) {
        __syncthreads();
        stage_w<64, 72>(gwh + ch * 8192, gwl + ch * 8192, wa, tid);
        {
            __nv_bfloat16* xh = xbh;
            __nv_bfloat16* xl = xbh + 64 * NPAD;
            const int off = (ch - 1) * d;
#pragma unroll 1
            for (int idx = tid; idx < 64 * NT; idx += THR) {
                int kk = idx >> 7, pp = idx & 127;
                int t0 = tb + pp + off;
                float v = ((unsigned)t0 < TT)
                    ? xin[(size_t)(b * RCH + kk) * TT + t0] : 0.f;
                __nv_bfloat16 h = __float2bfloat16(v);
                __nv_bfloat16 lo = __float2bfloat16(v - __bfloat162float(h));
                xh[kk * NPAD + pp] = h;
                xl[kk * NPAD + pp] = lo;
            }
        }
        __syncthreads();
        mma_chunk<72, 4>(acc, wa, wa + 128 * 72, xbh, xbh + 64 * NPAD, m0, n0);
    }

    // ===== GEMM1 aux (S=80) ==================================================
    __syncthreads();
    stage_w<80, 88>(gwh + 24576, gwl + 24576, wa, tid);
    {
        __nv_bfloat16* xh = xbh;
        __nv_bfloat16* xl = xbh + 80 * NPAD;
#pragma unroll 1
        for (int idx = tid; idx < ACH * NT; idx += THR) {
            int kk = idx >> 7, pp = idx & 127;
            float v = cond[(size_t)(b * ACH + kk) * TT + tb + pp];
            __nv_bfloat16 h = __float2bfloat16(v);
            __nv_bfloat16 lo = __float2bfloat16(v - __bfloat162float(h));
            xh[kk * NPAD + pp] = h;
            xl[kk * NPAD + pp] = lo;
        }
    }
    __syncthreads();
    mma_chunk<88, 5>(acc, wa, wa + 128 * 88, xbh, xbh + 80 * NPAD, m0, n0);

    // ===== H -> smem =========================================================
    __syncthreads();
#pragma unroll
    for (int nt = 0; nt < 4; nt++)
        wmma::store_matrix_sync(fsm + m0 * NPAD + n0 + 16 * nt, acc[nt],
                                NPAD, wmma::mem_row_major);
    __syncthreads();

    // ===== gate -> Z =========================================================
    {
        __nv_bfloat16* zh = xbh;
        __nv_bfloat16* zl = xbh + 64 * NPAD;
        const float* cbp = conv_b + l * GCH;
#pragma unroll 1
        for (int idx = tid; idx < 64 * NT; idx += THR) {
            int c = idx >> 7, pp = idx & 127;
            float a = fsm[c * NPAD + pp] + cbp[c];
            float g = fsm[(c + 64) * NPAD + pp] + cbp[c + 64];
            float z = gatef(a, g);
            __nv_bfloat16 h = __float2bfloat16(z);
            __nv_bfloat16 lo = __float2bfloat16(z - __bfloat162float(h));
            zh[c * NPAD + pp] = h;
            zl[c * NPAD + pp] = lo;
        }
    }
    __syncthreads();   // fsm (H) dead; stage OW over it

    stage_w<64, 72>(gwh + 34816, gwl + 34816, wa, tid);
#pragma unroll
    for (int i = 0; i < 4; i++) wmma::fill_fragment(acc[i], 0.f);
    __syncthreads();

    // ===== GEMM2: out projection (K=64) ======================================
    mma_chunk<72, 4>(acc, wa, wa + 128 * 72, xbh, xbh + 64 * NPAD, m0, n0);
    __syncthreads();
#pragma unroll
    for (int nt = 0; nt < 4; nt++)
        wmma::store_matrix_sync(fsm + m0 * NPAD + n0 + 16 * nt, acc[nt],
                                NPAD, wmma::mem_row_major);
    __syncthreads();

    // ===== epilogue: bias, mask, residual, skip ==============================
    {
        const float* obp = out_b + l * (RCH + SCH);
#pragma unroll 1
        for (int idx = tid; idx < 128 * NT; idx += THR) {
            int r = idx >> 7, pp = idx & 127;
            float o = fsm[r * NPAD + pp] + obp[r];
            float m = mask[p0 + pp];
            if (r < RCH) {
                size_t xi = ((size_t)(b * RCH + r) << 13) + tb + pp;
                xout[xi] = fmaf(o, m, xin[xi]);
            } else {
                size_t si = ((size_t)(b * SCH + r - RCH) << 13) + tb + pp;
                g_skip[si] += o * m;
            }
        }
    }
}

// ---------------------------------------------------------------------------
__global__ void k_last(const float* __restrict__ w1, const float* __restrict__ b1,
                       const float* __restrict__ w2, const float* __restrict__ b2,
                       float* __restrict__ out) {
    __shared__ float w1t[64 * 64];
    __shared__ float w2s[64];
    __shared__ float b1s[64];
    const int tid = threadIdx.x;
    for (int idx = tid; idx < 64 * 64; idx += 256) {
        int i = idx >> 6, j = idx & 63;
        w1t[i * 64 + j] = w1[j * 64 + i];
    }
    if (tid < 64) { w2s[tid] = w2[tid]; b1s[tid] = b1[tid]; }
    __syncthreads();

    const int p = blockIdx.x * 256 + tid;
    const int b = p >> 13;
    const int t = p & (TT - 1);

    float acc[64];
#pragma unroll
    for (int j = 0; j < 64; j++) acc[j] = b1s[j];

    const float* sp = g_skip + (size_t)b * SCH * TT + t;
    for (int i = 0; i < 64; i++) {
        float sv = fmaxf(sp[i * TT], 0.f);
#pragma unroll
        for (int j = 0; j < 64; j += 4) {
            float4 w = *(const float4*)(w1t + i * 64 + j);
            acc[j]     = fmaf(w.x, sv, acc[j]);
            acc[j + 1] = fmaf(w.y, sv, acc[j + 1]);
            acc[j + 2] = fmaf(w.z, sv, acc[j + 2]);
            acc[j + 3] = fmaf(w.w, sv, acc[j + 3]);
        }
    }
    float y = b2[0];
#pragma unroll
    for (int j = 0; j < 64; j++) y = fmaf(w2s[j], fmaxf(acc[j], 0.f), y);
    out[p] = y;
}

// ---------------------------------------------------------------------------
extern "C" void kernel_launch(void* const* d_in, const int* in_sizes, int n_in,
                              void* d_out, int out_size) {
    const float* x      = (const float*)d_in[0];
    const float* x_mask = (const float*)d_in[1];
    const float* c      = (const float*)d_in[2];
    const float* fw     = (const float*)d_in[3];
    const float* fb     = (const float*)d_in[4];
    const float* conv_w = (const float*)d_in[5];
    const float* conv_b = (const float*)d_in[6];
    const float* aux_w  = (const float*)d_in[7];
    const float* out_w  = (const float*)d_in[8];
    const float* out_b  = (const float*)d_in[9];
    const float* w1     = (const float*)d_in[10];
    const float* b1     = (const float*)d_in[11];
    const float* w2     = (const float*)d_in[12];
    const float* b2     = (const float*)d_in[13];

    cudaFuncSetAttribute(k_layer, cudaFuncAttributeMaxDynamicSharedMemorySize,
                         SMEM_TOTAL);

    int nprep = NLAYERS * WPERL;
    k_prep<<<(nprep + 511) / 512, 512>>>(conv_w, aux_w, out_w);
    k_first<<<(RCH * NPOS) / 512, 512>>>(x, fw, fb);

    for (int l = 0; l < NLAYERS; l++) {
        int d = 1 << (l % 10);
        k_layer<<<NPOS / NT, THR, SMEM_TOTAL>>>(
            l, d, l & 1, conv_b, out_b, c, x_mask);
    }

    k_last<<<NPOS / 256, 256>>>(w1, b1, w2, b2, (float*)d_out);
}